// round 2
// baseline (speedup 1.0000x reference)
#include <cuda_runtime.h>
#include <cstdint>

// Problem constants
#define BB  8
#define CC  96
#define HH  224
#define WW  224
#define NN  (HH*WW)     // 50176
#define H2  112
#define W2  112
#define NP  (H2*W2)     // 12544
#define KK  384         // 4*C
#define C2O 192         // 2*C
#define LN_EPS 1e-5f

typedef unsigned long long ull;

// Scratch: repacked per-pixel rows featP[b][p][k], k = q*96 + c  (154 MB)
__device__ float g_featP[(size_t)BB * NP * KK];
__device__ int   g_pos64;

// ---------------------------------------------------------------------------
// detect whether pos is int64 or int32 (jax x64 config unknown)
// int32 data read as int64 combines two xs values -> huge unless upper word 0;
// probability all 64 upper words are 0 under a random permutation is ~0.
// ---------------------------------------------------------------------------
__global__ void detect_pos_kernel(const void* pos) {
    if (threadIdx.x == 0 && blockIdx.x == 0) {
        const long long* p64 = (const long long*)pos;
        int ok = 1;
        for (int i = 0; i < 64; i++) {
            long long v = p64[i];
            if (v < 0 || v >= 224) { ok = 0; break; }
        }
        g_pos64 = ok;
    }
}

// ---------------------------------------------------------------------------
// write pos_out (float j, i) and zero mask_out (needed before atomicMax)
// ---------------------------------------------------------------------------
__global__ void init_posmask_kernel(float* pos_out, float* mask_out) {
    int idx = blockIdx.x * blockDim.x + threadIdx.x;
    if (idx >= BB * NP) return;
    int b = idx / NP, p = idx % NP;
    int i = p / W2, j = p % W2;
    pos_out[((size_t)b * 2 + 0) * NP + p] = (float)j;  // xs
    pos_out[((size_t)b * 2 + 1) * NP + p] = (float)i;  // ys
    mask_out[(size_t)b * NP + p] = 0.0f;
}

// ---------------------------------------------------------------------------
// Scatter-transpose: feat[b][c][n]*mask -> featP[b][p][q*96+c]
// Coalesced global reads (32 consecutive n per warp), smem transpose
// (pad 97 -> conflict-free), contiguous 384B row-segment writes.
// Also accumulates mask_out = max over quadrants (atomicMax on float bits).
// ---------------------------------------------------------------------------
__global__ __launch_bounds__(256) void scatter_kernel(
    const void* __restrict__ posv,
    const float* __restrict__ feat,
    const float* __restrict__ mask,
    float* mask_out /* may be null */)
{
    __shared__ float tileT[32][97];
    __shared__ float mval[32];
    __shared__ int   dstoff[32];

    int b  = blockIdx.y;
    int n0 = blockIdx.x * 32;
    int t  = threadIdx.x;

    if (t < 32) {
        int n = n0 + t;
        int x, y;
        if (g_pos64) {
            const long long* p64 = (const long long*)posv;
            x = (int)p64[n];
            y = (int)p64[NN + n];
        } else {
            const int* p32 = (const int*)posv;
            x = p32[n];
            y = p32[NN + n];
        }
        int p = (y >> 1) * W2 + (x >> 1);
        int q = (y & 1) + 2 * (x & 1);       // x0:ee=0 x1:oe=1 x2:eo=2 x3:oo=3
        dstoff[t] = p * KK + q * CC;
        float m = mask[(size_t)b * NN + n];
        mval[t] = m;
        if (mask_out)
            atomicMax((unsigned int*)&mask_out[(size_t)b * NP + p],
                      __float_as_uint(m));
    }
    __syncthreads();

    const float* fb = feat + (size_t)b * CC * NN;
    for (int e = t; e < CC * 32; e += 256) {
        int c = e >> 5, nl = e & 31;                 // coalesced 128B reads
        tileT[nl][c] = fb[(size_t)c * NN + n0 + nl] * mval[nl];
    }
    __syncthreads();

    float* outb = g_featP + (size_t)b * NP * KK;
    for (int e = t; e < 32 * CC; e += 256) {
        int nl = e / CC, c = e % CC;                 // contiguous 384B segments
        outb[dstoff[nl] + c] = tileT[nl][c];
    }
}

// ---------------------------------------------------------------------------
// packed f32x2 helpers (FFMA2: 2x fp32 FMA throughput, PTX-only)
// ---------------------------------------------------------------------------
__device__ __forceinline__ ull f32x2_fma(ull a, ull b, ull c) {
    ull d;
    asm("fma.rn.f32x2 %0, %1, %2, %3;" : "=l"(d) : "l"(a), "l"(b), "l"(c));
    return d;
}
__device__ __forceinline__ float f32x2_hsum(ull a) {
    float lo, hi;
    asm("mov.b64 {%0,%1}, %2;" : "=f"(lo), "=f"(hi) : "l"(a));
    return lo + hi;
}

// ---------------------------------------------------------------------------
// LayerNorm(384) + GEMM [112 pixels x 384] @ [384 x 192]^T per block.
// 384 threads: thread t owns c2 = t%96 and c2+96 (reuses each xm load twice),
// quarter = t/96 -> 28 pixels. acc in packed f32x2 (even/odd k halves).
// Warp-uniform (p,k) smem reads -> pure broadcast, conflict-free.
// ---------------------------------------------------------------------------
__global__ __launch_bounds__(384, 1) void ln_gemm_kernel(
    const float* __restrict__ norm_w,
    const float* __restrict__ norm_b,
    const float* __restrict__ red_w,
    float* __restrict__ out)
{
    extern __shared__ float sm[];              // 112 * 384 floats = 168 KB
    const int PT = 112;
    int b     = blockIdx.y;
    int ptile = blockIdx.x;                    // 0..111
    int t     = threadIdx.x;

    // --- load 112 contiguous rows (float4, fully coalesced) ---
    const float4* src4 = (const float4*)(g_featP + ((size_t)b * NP + (size_t)ptile * PT) * KK);
    float4* sm4 = (float4*)sm;
    #pragma unroll 4
    for (int e = t; e < PT * KK / 4; e += 384) sm4[e] = src4[e];
    __syncthreads();

    // --- LayerNorm: one warp per row ---
    int warp = t >> 5, lane = t & 31;
    for (int row = warp; row < PT; row += 12) {
        float* r = sm + row * KK;
        float s = 0.f, ss = 0.f;
        #pragma unroll
        for (int k = lane; k < KK; k += 32) { float v = r[k]; s += v; ss += v * v; }
        #pragma unroll
        for (int o = 16; o; o >>= 1) {
            s  += __shfl_xor_sync(0xFFFFFFFFu, s,  o);
            ss += __shfl_xor_sync(0xFFFFFFFFu, ss, o);
        }
        float mu  = s * (1.f / KK);
        float var = ss * (1.f / KK) - mu * mu;
        float sc  = rsqrtf(var + LN_EPS);
        #pragma unroll
        for (int k = lane; k < KK; k += 32) {
            float v = r[k];
            r[k] = (v - mu) * sc * __ldg(norm_w + k) + __ldg(norm_b + k);
        }
    }
    __syncthreads();

    // --- GEMM ---
    int c2      = t % 96;
    int quarter = t / 96;
    int p0      = quarter * 28;

    const ull* w0p = (const ull*)(red_w + (size_t)c2 * KK);          // pairs (k,k+1)
    const ull* w1p = (const ull*)(red_w + (size_t)(c2 + 96) * KK);

    ull acc0[28], acc1[28];
    #pragma unroll
    for (int p = 0; p < 28; p++) { acc0[p] = 0ull; acc1[p] = 0ull; }

    for (int kc = 0; kc < 192; kc += 4) {      // 192 f32x2 pairs over K=384
        ull w0r[4], w1r[4];
        #pragma unroll
        for (int j = 0; j < 4; j++) { w0r[j] = w0p[kc + j]; w1r[j] = w1p[kc + j]; }
        #pragma unroll
        for (int p = 0; p < 28; p++) {
            const ull* x = (const ull*)(sm + (p0 + p) * KK) + kc;
            #pragma unroll
            for (int j = 0; j < 4; j++) {
                ull xv = x[j];                              // LDS.64 broadcast
                acc0[p] = f32x2_fma(xv, w0r[j], acc0[p]);
                acc1[p] = f32x2_fma(xv, w1r[j], acc1[p]);
            }
        }
    }

    float* ob = out + (size_t)b * C2O * NP + (size_t)ptile * PT;
    #pragma unroll
    for (int p = 0; p < 28; p++) {
        ob[(size_t)c2 * NP + p0 + p]        = f32x2_hsum(acc0[p]);
        ob[(size_t)(c2 + 96) * NP + p0 + p] = f32x2_hsum(acc1[p]);
    }
}

// ---------------------------------------------------------------------------
extern "C" void kernel_launch(void* const* d_in, const int* in_sizes, int n_in,
                              void* d_out, int out_size) {
    const void*  pos    = d_in[0];
    const float* feat   = (const float*)d_in[1];
    const float* mask   = (const float*)d_in[2];
    const float* norm_w = (const float*)d_in[3];
    const float* norm_b = (const float*)d_in[4];
    const float* red_w  = (const float*)d_in[5];

    float* outf = (float*)d_out;
    const int n_pos  = BB * 2 * NP;       // 200704
    const int n_main = BB * C2O * NP;     // 19267584
    const int n_mask = BB * NP;           // 100352

    float* pos_out  = nullptr;
    float* out_main = outf;
    float* mask_out = nullptr;
    if (out_size == n_pos + n_main + n_mask) {
        pos_out  = outf;
        out_main = outf + n_pos;
        mask_out = out_main + n_main;
    }

    cudaFuncSetAttribute(ln_gemm_kernel,
                         cudaFuncAttributeMaxDynamicSharedMemorySize,
                         112 * KK * (int)sizeof(float));

    detect_pos_kernel<<<1, 1>>>(pos);
    if (pos_out)
        init_posmask_kernel<<<(BB * NP + 255) / 256, 256>>>(pos_out, mask_out);
    scatter_kernel<<<dim3(NN / 32, BB), 256>>>(pos, feat, mask, mask_out);
    ln_gemm_kernel<<<dim3(NP / 112, BB), 384, 112 * KK * sizeof(float)>>>(
        norm_w, norm_b, red_w, out_main);
}

// round 6
// speedup vs baseline: 4.8908x; 4.8908x over previous
#include <cuda_runtime.h>
#include <cuda_fp16.h>
#include <cstdint>

// Problem constants
#define BB  8
#define CC  96
#define HH  224
#define WW  224
#define NN  (HH*WW)     // 50176
#define H2  112
#define W2  112
#define NP  (H2*W2)     // 12544
#define KK  384         // 4*C
#define C2O 192         // 2*C
#define LN_EPS 1e-5f

#define MT     128               // M tile per block
#define NTILES (NP / MT)         // 98
#define KC     64                // K chunk
#define NCHUNK (KK / KC)         // 6

// ---------------------------------------------------------------------------
// Global scratch
// ---------------------------------------------------------------------------
__device__ float g_featP[(size_t)BB * NP * KK];                 // 154 MB
__device__ __align__(16) __half g_A[(size_t)BB * NP * KK];      // 77 MB (post-LN fp16)
__device__ __align__(16) __half g_B[(size_t)C2O * KK];          // red_w fp16
__device__ int g_pos64;

// ---------------------------------------------------------------------------
// helpers
// ---------------------------------------------------------------------------
__device__ __forceinline__ uint32_t smem_u32(const void* p) {
    uint32_t a;
    asm("{ .reg .u64 t; cvta.to.shared.u64 t, %1; cvt.u32.u64 %0, t; }" : "=r"(a) : "l"(p));
    return a;
}
__device__ __forceinline__ uint32_t swz(uint32_t off) {   // SW128: bits[6:4] ^= bits[9:7]
    return off ^ ((off >> 3) & 0x70);
}
__device__ __forceinline__ void cpa16(uint32_t dst, const void* src) {
    asm volatile("cp.async.cg.shared.global [%0], [%1], 16;" :: "r"(dst), "l"(src) : "memory");
}
#define CP_COMMIT() asm volatile("cp.async.commit_group;" ::: "memory")
template <int N> __device__ __forceinline__ void cp_wait() {
    asm volatile("cp.async.wait_group %0;" :: "n"(N) : "memory");
}
__device__ __forceinline__ void ldm_x4(uint32_t* r, uint32_t addr) {
    asm volatile("ldmatrix.sync.aligned.m8n8.x4.shared.b16 {%0,%1,%2,%3}, [%4];"
                 : "=r"(r[0]), "=r"(r[1]), "=r"(r[2]), "=r"(r[3]) : "r"(addr));
}
__device__ __forceinline__ void ldm_x2(uint32_t* r, uint32_t addr) {
    asm volatile("ldmatrix.sync.aligned.m8n8.x2.shared.b16 {%0,%1}, [%2];"
                 : "=r"(r[0]), "=r"(r[1]) : "r"(addr));
}
__device__ __forceinline__ void mma16816(float* c, const uint32_t* a, const uint32_t* b) {
    asm volatile(
        "mma.sync.aligned.m16n8k16.row.col.f32.f16.f16.f32 "
        "{%0,%1,%2,%3}, {%4,%5,%6,%7}, {%8,%9}, {%0,%1,%2,%3};"
        : "+f"(c[0]), "+f"(c[1]), "+f"(c[2]), "+f"(c[3])
        : "r"(a[0]), "r"(a[1]), "r"(a[2]), "r"(a[3]), "r"(b[0]), "r"(b[1]));
}

// ---------------------------------------------------------------------------
// pos dtype detection
// ---------------------------------------------------------------------------
__global__ void detect_pos_kernel(const void* pos) {
    if (threadIdx.x == 0 && blockIdx.x == 0) {
        const long long* p64 = (const long long*)pos;
        int ok = 1;
        for (int i = 0; i < 64; i++) {
            long long v = p64[i];
            if (v < 0 || v >= 224) { ok = 0; break; }
        }
        g_pos64 = ok;
    }
}

// ---------------------------------------------------------------------------
// pos_out + zero mask_out
// ---------------------------------------------------------------------------
__global__ void init_posmask_kernel(float* pos_out, float* mask_out) {
    int idx = blockIdx.x * blockDim.x + threadIdx.x;
    if (idx >= BB * NP) return;
    int b = idx / NP, p = idx % NP;
    int i = p / W2, j = p % W2;
    pos_out[((size_t)b * 2 + 0) * NP + p] = (float)j;
    pos_out[((size_t)b * 2 + 1) * NP + p] = (float)i;
    mask_out[(size_t)b * NP + p] = 0.0f;
}

// ---------------------------------------------------------------------------
// Scatter-transpose: feat[b][c][n]*mask -> featP[b][p][q*96+c]
// ---------------------------------------------------------------------------
__global__ __launch_bounds__(256) void scatter_kernel(
    const void* __restrict__ posv,
    const float* __restrict__ feat,
    const float* __restrict__ mask,
    float* mask_out)
{
    __shared__ float tileT[32][97];
    __shared__ float mval[32];
    __shared__ int   dstoff[32];

    int b  = blockIdx.y;
    int n0 = blockIdx.x * 32;
    int t  = threadIdx.x;

    if (t < 32) {
        int n = n0 + t;
        int x, y;
        if (g_pos64) {
            const long long* p64 = (const long long*)posv;
            x = (int)p64[n];
            y = (int)p64[NN + n];
        } else {
            const int* p32 = (const int*)posv;
            x = p32[n];
            y = p32[NN + n];
        }
        int p = (y >> 1) * W2 + (x >> 1);
        int q = (y & 1) + 2 * (x & 1);
        dstoff[t] = p * KK + q * CC;
        float m = mask[(size_t)b * NN + n];
        mval[t] = m;
        if (mask_out)
            atomicMax((unsigned int*)&mask_out[(size_t)b * NP + p],
                      __float_as_uint(m));
    }
    __syncthreads();

    const float* fb = feat + (size_t)b * CC * NN;
    for (int e = t; e < CC * 32; e += 256) {
        int c = e >> 5, nl = e & 31;
        tileT[nl][c] = fb[(size_t)c * NN + n0 + nl] * mval[nl];
    }
    __syncthreads();

    float* outb = g_featP + (size_t)b * NP * KK;
    for (int e = t; e < 32 * CC; e += 256) {
        int nl = e / CC, c = e % CC;
        outb[dstoff[nl] + c] = tileT[nl][c];
    }
}

// ---------------------------------------------------------------------------
// LayerNorm + fp16 convert; row-major g_A[row][k]. One warp per row.
// ---------------------------------------------------------------------------
__global__ __launch_bounds__(256) void ln_half_kernel(
    const float* __restrict__ norm_w,
    const float* __restrict__ norm_b)
{
    int row  = blockIdx.x * 8 + (threadIdx.x >> 5);
    int lane = threadIdx.x & 31;

    const float4* src4 = (const float4*)(g_featP + (size_t)row * KK);

    float4 v[3];
    float s = 0.f, ss = 0.f;
    #pragma unroll
    for (int it = 0; it < 3; it++) {
        float4 x = src4[lane + 32 * it];
        v[it] = x;
        s  += x.x + x.y + x.z + x.w;
        ss += x.x*x.x + x.y*x.y + x.z*x.z + x.w*x.w;
    }
    #pragma unroll
    for (int o = 16; o; o >>= 1) {
        s  += __shfl_xor_sync(0xFFFFFFFFu, s,  o);
        ss += __shfl_xor_sync(0xFFFFFFFFu, ss, o);
    }
    float mu  = s * (1.f / KK);
    float var = ss * (1.f / KK) - mu * mu;
    float sc  = rsqrtf(var + LN_EPS);

    __half* dst = g_A + (size_t)row * KK;
    #pragma unroll
    for (int it = 0; it < 3; it++) {
        int g = lane + 32 * it;
        int k = 4 * g;
        float4 w4  = ((const float4*)norm_w)[g];
        float4 bi4 = ((const float4*)norm_b)[g];
        float4 x = v[it];
        float n0 = (x.x - mu) * sc * w4.x + bi4.x;
        float n1 = (x.y - mu) * sc * w4.y + bi4.y;
        float n2 = (x.z - mu) * sc * w4.z + bi4.z;
        float n3 = (x.w - mu) * sc * w4.w + bi4.w;
        union { uint2 u; __half2 h[2]; } pk;
        pk.h[0] = __floats2half2_rn(n0, n1);
        pk.h[1] = __floats2half2_rn(n2, n3);
        *(uint2*)(dst + k) = pk.u;
    }
}

// ---------------------------------------------------------------------------
// red_w -> fp16
// ---------------------------------------------------------------------------
__global__ void bhalf_kernel(const float* __restrict__ red_w) {
    int idx = blockIdx.x * blockDim.x + threadIdx.x;
    if (idx >= C2O * (KK / 4)) return;
    float4 x = ((const float4*)red_w)[idx];
    union { uint2 u; __half2 h[2]; } pk;
    pk.h[0] = __floats2half2_rn(x.x, x.y);
    pk.h[1] = __floats2half2_rn(x.z, x.w);
    *(uint2*)(g_B + 4 * (size_t)idx) = pk.u;
}

// ---------------------------------------------------------------------------
// HMMA GEMM: out[b][c2][p] = sum_k A[p][k] * W[c2][k]
// Block 128(M) x 192(N); 8 warps = 4(M) x 2(N) of 32x96 warp tiles.
// 2-stage cp.async pipeline, K chunks of 64.
// ---------------------------------------------------------------------------
#define STAGE_A (MT * KC * 2)            // 16384 B
#define STAGE_B (C2O * KC * 2)           // 24576 B
#define STAGE_BYTES (STAGE_A + STAGE_B)  // 40960 B
#define GEMM_SMEM (2 * STAGE_BYTES)      // 81920 B

__global__ __launch_bounds__(256, 1) void gemm_hmma_kernel(float* __restrict__ out)
{
    extern __shared__ __align__(128) unsigned char smraw[];
    uint32_t base = smem_u32(smraw);

    int t     = threadIdx.x;
    int lane  = t & 31;
    int wid   = t >> 5;
    int ptile = blockIdx.x;
    int b     = blockIdx.y;
    int warp_m = wid >> 1;       // 0..3
    int warp_n = wid & 1;        // 0..1

    const __half* Ag = g_A + ((size_t)b * NP + (size_t)ptile * MT) * KK;
    const __half* Bg = g_B;

    // --- stage loader ---
    auto load_stage = [&](int s, int c) {
        uint32_t st = base + s * STAGE_BYTES;
        const __half* Ac = Ag + c * KC;
        #pragma unroll
        for (int e = t; e < MT * 8; e += 256) {          // 1024 x 16B
            int row = e >> 3, ch = e & 7;
            cpa16(st + swz(row * 128 + ch * 16), Ac + (size_t)row * KK + ch * 8);
        }
        const __half* Bc = Bg + c * KC;
        #pragma unroll
        for (int e = t; e < C2O * 8; e += 256) {         // 1536 x 16B
            int row = e >> 3, ch = e & 7;
            cpa16(st + STAGE_A + swz(row * 128 + ch * 16), Bc + (size_t)row * KK + ch * 8);
        }
        CP_COMMIT();
    };

    float acc[2][12][4];
    #pragma unroll
    for (int mt = 0; mt < 2; mt++)
        #pragma unroll
        for (int nt = 0; nt < 12; nt++)
            #pragma unroll
            for (int j = 0; j < 4; j++) acc[mt][nt][j] = 0.f;

    load_stage(0, 0);

    int l4 = lane & 15;
    for (int c = 0; c < NCHUNK; c++) {
        if (c + 1 < NCHUNK) { load_stage((c + 1) & 1, c + 1); cp_wait<1>(); }
        else                { cp_wait<0>(); }
        __syncthreads();

        uint32_t Ab = base + (c & 1) * STAGE_BYTES;
        uint32_t Bb = Ab + STAGE_A;

        #pragma unroll
        for (int step = 0; step < 4; step++) {
            int k0 = step * 16;
            uint32_t a[2][4];
            #pragma unroll
            for (int mt = 0; mt < 2; mt++) {
                int row = warp_m * 32 + mt * 16 + l4;
                int kk  = k0 + ((lane >> 4) << 3);       // lanes16-31 -> +8
                ldm_x4(a[mt], Ab + swz((uint32_t)(row * 128 + kk * 2)));
            }
            #pragma unroll
            for (int nt = 0; nt < 12; nt++) {
                int n  = warp_n * 96 + nt * 8 + (l4 & 7);
                int kk = k0 + ((l4 >> 3) << 3);          // lanes8-15 -> +8
                uint32_t bfr[2];
                ldm_x2(bfr, Bb + swz((uint32_t)(n * 128 + kk * 2)));
                mma16816(acc[0][nt], a[0], bfr);
                mma16816(acc[1][nt], a[1], bfr);
            }
        }
        __syncthreads();
    }

    // --- epilogue ---
    int gid  = lane >> 2;
    int tid4 = lane & 3;
    float* ob = out + (size_t)b * C2O * NP;
    #pragma unroll
    for (int mt = 0; mt < 2; mt++) {
        int p = ptile * MT + warp_m * 32 + mt * 16 + gid;
        #pragma unroll
        for (int nt = 0; nt < 12; nt++) {
            int col = warp_n * 96 + nt * 8 + tid4 * 2;
            float* o0 = ob + (size_t)col * NP + p;
            o0[0]          = acc[mt][nt][0];
            o0[NP]         = acc[mt][nt][1];
            o0[8]          = acc[mt][nt][2];
            o0[NP + 8]     = acc[mt][nt][3];
        }
    }
}

// ---------------------------------------------------------------------------
extern "C" void kernel_launch(void* const* d_in, const int* in_sizes, int n_in,
                              void* d_out, int out_size) {
    const void*  pos    = d_in[0];
    const float* feat   = (const float*)d_in[1];
    const float* mask   = (const float*)d_in[2];
    const float* norm_w = (const float*)d_in[3];
    const float* norm_b = (const float*)d_in[4];
    const float* red_w  = (const float*)d_in[5];

    float* outf = (float*)d_out;
    const int n_pos  = BB * 2 * NP;
    const int n_main = BB * C2O * NP;
    const int n_mask = BB * NP;

    float* pos_out  = nullptr;
    float* out_main = outf;
    float* mask_out = nullptr;
    if (out_size == n_pos + n_main + n_mask) {
        pos_out  = outf;
        out_main = outf + n_pos;
        mask_out = out_main + n_main;
    }

    cudaFuncSetAttribute(gemm_hmma_kernel,
                         cudaFuncAttributeMaxDynamicSharedMemorySize, GEMM_SMEM);

    detect_pos_kernel<<<1, 1>>>(pos);
    if (pos_out)
        init_posmask_kernel<<<(BB * NP + 255) / 256, 256>>>(pos_out, mask_out);
    bhalf_kernel<<<(C2O * (KK/4) + 255) / 256, 256>>>(red_w);
    scatter_kernel<<<dim3(NN / 32, BB), 256>>>(pos, feat, mask, mask_out);
    ln_half_kernel<<<(BB * NP) / 8, 256>>>(norm_w, norm_b);
    gemm_hmma_kernel<<<dim3(NTILES, BB), 256, GEMM_SMEM>>>(out_main);
}

// round 7
// speedup vs baseline: 7.3310x; 1.4990x over previous
#include <cuda_runtime.h>
#include <cuda_fp16.h>
#include <cstdint>

// Problem constants
#define BB  8
#define CC  96
#define HH  224
#define WW  224
#define NN  (HH*WW)     // 50176
#define H2  112
#define W2  112
#define NP  (H2*W2)     // 12544
#define KK  384         // 4*C
#define C2O 192         // 2*C
#define LN_EPS 1e-5f

#define MT     128               // M tile per block
#define NTILES (NP / MT)         // 98
#define KC     64                // K chunk
#define NCHUNK (KK / KC)         // 6

// ---------------------------------------------------------------------------
// Global scratch
// ---------------------------------------------------------------------------
__device__ __align__(16) __half g_A[(size_t)BB * NP * KK];      // 77 MB masked feat fp16
__device__ __align__(16) __half g_B[(size_t)C2O * KK];          // W' = norm_w * red_w (fp16)
__device__ float  g_s1[C2O];
__device__ float  g_s2[C2O];
__device__ __align__(16) float  g_qstats[(size_t)BB * NP * 4 * 2]; // per-quadrant (sum, sumsq)
__device__ __align__(8)  float2 g_stats[(size_t)BB * NP];          // (mu, rstd)
__device__ int g_pos64;

// ---------------------------------------------------------------------------
// helpers
// ---------------------------------------------------------------------------
__device__ __forceinline__ uint32_t smem_u32(const void* p) {
    uint32_t a;
    asm("{ .reg .u64 t; cvta.to.shared.u64 t, %1; cvt.u32.u64 %0, t; }" : "=r"(a) : "l"(p));
    return a;
}
__device__ __forceinline__ uint32_t swz(uint32_t off) {   // SW128: bits[6:4] ^= bits[9:7]
    return off ^ ((off >> 3) & 0x70);
}
__device__ __forceinline__ void cpa16(uint32_t dst, const void* src) {
    asm volatile("cp.async.cg.shared.global [%0], [%1], 16;" :: "r"(dst), "l"(src) : "memory");
}
#define CP_COMMIT() asm volatile("cp.async.commit_group;" ::: "memory")
template <int N> __device__ __forceinline__ void cp_wait() {
    asm volatile("cp.async.wait_group %0;" :: "n"(N) : "memory");
}
__device__ __forceinline__ void ldm_x4(uint32_t* r, uint32_t addr) {
    asm volatile("ldmatrix.sync.aligned.m8n8.x4.shared.b16 {%0,%1,%2,%3}, [%4];"
                 : "=r"(r[0]), "=r"(r[1]), "=r"(r[2]), "=r"(r[3]) : "r"(addr));
}
__device__ __forceinline__ void ldm_x2(uint32_t* r, uint32_t addr) {
    asm volatile("ldmatrix.sync.aligned.m8n8.x2.shared.b16 {%0,%1}, [%2];"
                 : "=r"(r[0]), "=r"(r[1]) : "r"(addr));
}
__device__ __forceinline__ void mma16816(float* c, const uint32_t* a, const uint32_t* b) {
    asm volatile(
        "mma.sync.aligned.m16n8k16.row.col.f32.f16.f16.f32 "
        "{%0,%1,%2,%3}, {%4,%5,%6,%7}, {%8,%9}, {%0,%1,%2,%3};"
        : "+f"(c[0]), "+f"(c[1]), "+f"(c[2]), "+f"(c[3])
        : "r"(a[0]), "r"(a[1]), "r"(a[2]), "r"(a[3]), "r"(b[0]), "r"(b[1]));
}

// ---------------------------------------------------------------------------
// pos dtype detection
// ---------------------------------------------------------------------------
__global__ void detect_pos_kernel(const void* pos) {
    if (threadIdx.x == 0 && blockIdx.x == 0) {
        const long long* p64 = (const long long*)pos;
        int ok = 1;
        for (int i = 0; i < 64; i++) {
            long long v = p64[i];
            if (v < 0 || v >= 224) { ok = 0; break; }
        }
        g_pos64 = ok;
    }
}

// ---------------------------------------------------------------------------
// pos_out + zero mask_out
// ---------------------------------------------------------------------------
__global__ void init_posmask_kernel(float* pos_out, float* mask_out) {
    int idx = blockIdx.x * blockDim.x + threadIdx.x;
    if (idx >= BB * NP) return;
    int b = idx / NP, p = idx % NP;
    int i = p / W2, j = p % W2;
    pos_out[((size_t)b * 2 + 0) * NP + p] = (float)j;
    pos_out[((size_t)b * 2 + 1) * NP + p] = (float)i;
    mask_out[(size_t)b * NP + p] = 0.0f;
}

// ---------------------------------------------------------------------------
// Scatter-transpose + fp16 convert + per-quadrant LN partial stats.
// feat[b][c][n]*mask -> g_A[b][p][q*96+c] (fp16)
// g_qstats[b][p][q] = (sum, sumsq) over the 96 channels of that quadrant.
// ---------------------------------------------------------------------------
__global__ __launch_bounds__(256) void scatter_kernel(
    const void* __restrict__ posv,
    const float* __restrict__ feat,
    const float* __restrict__ mask,
    float* mask_out)
{
    __shared__ float tileT[32][97];
    __shared__ float mval[32];
    __shared__ int   dstP[32], dstQ[32];

    int b  = blockIdx.y;
    int n0 = blockIdx.x * 32;
    int t  = threadIdx.x;

    if (t < 32) {
        int n = n0 + t;
        int x, y;
        if (g_pos64) {
            const long long* p64 = (const long long*)posv;
            x = (int)p64[n];
            y = (int)p64[NN + n];
        } else {
            const int* p32 = (const int*)posv;
            x = p32[n];
            y = p32[NN + n];
        }
        int p = (y >> 1) * W2 + (x >> 1);
        int q = (y & 1) + 2 * (x & 1);
        dstP[t] = p;
        dstQ[t] = q;
        float m = mask[(size_t)b * NN + n];
        mval[t] = m;
        if (mask_out)
            atomicMax((unsigned int*)&mask_out[(size_t)b * NP + p],
                      __float_as_uint(m));
    }
    __syncthreads();

    const float* fb = feat + (size_t)b * CC * NN;
    #pragma unroll
    for (int e = t; e < CC * 32; e += 256) {
        int c = e >> 5, nl = e & 31;
        tileT[nl][c] = fb[(size_t)c * NN + n0 + nl] * mval[nl];
    }
    __syncthreads();

    // --- per-quadrant stats: 8 threads per point ---
    {
        int nl = t >> 3, l8 = t & 7;
        float s = 0.f, q = 0.f;
        #pragma unroll
        for (int j = 0; j < 12; j++) {
            float v = tileT[nl][l8 * 12 + j];
            s += v; q += v * v;
        }
        #pragma unroll
        for (int o = 4; o; o >>= 1) {
            s += __shfl_xor_sync(0xFFFFFFFFu, s, o);
            q += __shfl_xor_sync(0xFFFFFFFFu, q, o);
        }
        if (l8 == 0) {
            size_t si = ((size_t)b * NP + dstP[nl]) * 4 + dstQ[nl];
            ((float2*)g_qstats)[si] = make_float2(s, q);
        }
    }

    // --- fp16 convert + scattered 192B-segment writes ---
    __half2* outb = (__half2*)(g_A + (size_t)b * NP * KK);
    #pragma unroll
    for (int e = t; e < 32 * 48; e += 256) {
        int nl = e / 48, h = e % 48;
        int c = 2 * h;
        __half2 v = __floats2half2_rn(tileT[nl][c], tileT[nl][c + 1]);
        outb[(size_t)dstP[nl] * (KK / 2) + dstQ[nl] * (CC / 2) + h] = v;
    }
}

// ---------------------------------------------------------------------------
// Fold 4 quadrant partials -> (mu, rstd) per merged pixel.
// ---------------------------------------------------------------------------
__global__ void stats_kernel() {
    int idx = blockIdx.x * blockDim.x + threadIdx.x;
    if (idx >= BB * NP) return;
    const float4* p4 = (const float4*)(g_qstats + (size_t)idx * 8);
    float4 a = p4[0], c = p4[1];
    float s = a.x + a.z + c.x + c.z;
    float q = a.y + a.w + c.y + c.w;
    float mu  = s * (1.f / KK);
    float var = q * (1.f / KK) - mu * mu;
    g_stats[idx] = make_float2(mu, rsqrtf(var + LN_EPS));
}

// ---------------------------------------------------------------------------
// W' = norm_w * red_w (fp16), s1 = sum_k W'(rounded), s2 = sum_k norm_b*red_w
// One warp per output channel c.
// ---------------------------------------------------------------------------
__global__ __launch_bounds__(256) void wprep_kernel(
    const float* __restrict__ norm_w,
    const float* __restrict__ norm_b,
    const float* __restrict__ red_w)
{
    int wid = threadIdx.x >> 5, lane = threadIdx.x & 31;
    int c = blockIdx.x * 8 + wid;
    if (c >= C2O) return;
    const float* rw = red_w + (size_t)c * KK;
    float s1 = 0.f, s2 = 0.f;
    #pragma unroll
    for (int j = 0; j < 12; j++) {
        int k = lane + 32 * j;
        float w = norm_w[k], r = rw[k];
        __half wh = __float2half_rn(w * r);
        g_B[(size_t)c * KK + k] = wh;
        s1 += __half2float(wh);
        s2 += norm_b[k] * r;
    }
    #pragma unroll
    for (int o = 16; o; o >>= 1) {
        s1 += __shfl_xor_sync(0xFFFFFFFFu, s1, o);
        s2 += __shfl_xor_sync(0xFFFFFFFFu, s2, o);
    }
    if (lane == 0) { g_s1[c] = s1; g_s2[c] = s2; }
}

// ---------------------------------------------------------------------------
// HMMA GEMM on raw masked feat (fp16) with LN folded into the epilogue:
// out[b][c][p] = sc_p * (acc - mu_p * s1[c]) + s2[c]
// Block 128(M) x 192(N); 8 warps = 4(M) x 2(N); 2-stage cp.async, KC=64.
// ---------------------------------------------------------------------------
#define STAGE_A (MT * KC * 2)            // 16384 B
#define STAGE_B (C2O * KC * 2)           // 24576 B
#define STAGE_BYTES (STAGE_A + STAGE_B)  // 40960 B
#define GEMM_SMEM (2 * STAGE_BYTES + MT * 8)   // + 128 float2 stats

__global__ __launch_bounds__(256, 1) void gemm_hmma_kernel(float* __restrict__ out)
{
    extern __shared__ __align__(128) unsigned char smraw[];
    uint32_t base = smem_u32(smraw);
    float2* sMS = (float2*)(smraw + 2 * STAGE_BYTES);

    int t     = threadIdx.x;
    int lane  = t & 31;
    int wid   = t >> 5;
    int ptile = blockIdx.x;
    int b     = blockIdx.y;
    int warp_m = wid >> 1;       // 0..3
    int warp_n = wid & 1;        // 0..1

    // per-row (mu, rstd) into smem
    if (t < MT) {
        float2 sq = g_stats[(size_t)b * NP + (size_t)ptile * MT + t];
        sMS[t] = sq;
    }

    const __half* Ag = g_A + ((size_t)b * NP + (size_t)ptile * MT) * KK;
    const __half* Bg = g_B;

    auto load_stage = [&](int s, int c) {
        uint32_t st = base + s * STAGE_BYTES;
        const __half* Ac = Ag + c * KC;
        #pragma unroll
        for (int e = t; e < MT * 8; e += 256) {
            int row = e >> 3, ch = e & 7;
            cpa16(st + swz(row * 128 + ch * 16), Ac + (size_t)row * KK + ch * 8);
        }
        const __half* Bc = Bg + c * KC;
        #pragma unroll
        for (int e = t; e < C2O * 8; e += 256) {
            int row = e >> 3, ch = e & 7;
            cpa16(st + STAGE_A + swz(row * 128 + ch * 16), Bc + (size_t)row * KK + ch * 8);
        }
        CP_COMMIT();
    };

    float acc[2][12][4];
    #pragma unroll
    for (int mt = 0; mt < 2; mt++)
        #pragma unroll
        for (int nt = 0; nt < 12; nt++)
            #pragma unroll
            for (int j = 0; j < 4; j++) acc[mt][nt][j] = 0.f;

    load_stage(0, 0);

    int l4 = lane & 15;
    for (int c = 0; c < NCHUNK; c++) {
        if (c + 1 < NCHUNK) { load_stage((c + 1) & 1, c + 1); cp_wait<1>(); }
        else                { cp_wait<0>(); }
        __syncthreads();

        uint32_t Ab = base + (c & 1) * STAGE_BYTES;
        uint32_t Bb = Ab + STAGE_A;

        #pragma unroll
        for (int step = 0; step < 4; step++) {
            int k0 = step * 16;
            uint32_t a[2][4];
            #pragma unroll
            for (int mt = 0; mt < 2; mt++) {
                int row = warp_m * 32 + mt * 16 + l4;
                int kk  = k0 + ((lane >> 4) << 3);
                ldm_x4(a[mt], Ab + swz((uint32_t)(row * 128 + kk * 2)));
            }
            #pragma unroll
            for (int nt = 0; nt < 12; nt++) {
                int n  = warp_n * 96 + nt * 8 + (l4 & 7);
                int kk = k0 + ((l4 >> 3) << 3);
                uint32_t bfr[2];
                ldm_x2(bfr, Bb + swz((uint32_t)(n * 128 + kk * 2)));
                mma16816(acc[0][nt], a[0], bfr);
                mma16816(acc[1][nt], a[1], bfr);
            }
        }
        __syncthreads();
    }

    // --- epilogue with LN folding ---
    int gid  = lane >> 2;
    int tid4 = lane & 3;
    float* ob = out + (size_t)b * C2O * NP;
    #pragma unroll
    for (int mt = 0; mt < 2; mt++) {
        int rl = warp_m * 32 + mt * 16 + gid;
        float2 ms0 = sMS[rl];
        float2 ms1 = sMS[rl + 8];
        int p = ptile * MT + rl;
        #pragma unroll
        for (int nt = 0; nt < 12; nt++) {
            int col = warp_n * 96 + nt * 8 + tid4 * 2;
            float s1a = __ldg(g_s1 + col), s1b = __ldg(g_s1 + col + 1);
            float s2a = __ldg(g_s2 + col), s2b = __ldg(g_s2 + col + 1);
            float* o0 = ob + (size_t)col * NP + p;
            o0[0]      = ms0.y * (acc[mt][nt][0] - ms0.x * s1a) + s2a;
            o0[NP]     = ms0.y * (acc[mt][nt][1] - ms0.x * s1b) + s2b;
            o0[8]      = ms1.y * (acc[mt][nt][2] - ms1.x * s1a) + s2a;
            o0[NP + 8] = ms1.y * (acc[mt][nt][3] - ms1.x * s1b) + s2b;
        }
    }
}

// ---------------------------------------------------------------------------
extern "C" void kernel_launch(void* const* d_in, const int* in_sizes, int n_in,
                              void* d_out, int out_size) {
    const void*  pos    = d_in[0];
    const float* feat   = (const float*)d_in[1];
    const float* mask   = (const float*)d_in[2];
    const float* norm_w = (const float*)d_in[3];
    const float* norm_b = (const float*)d_in[4];
    const float* red_w  = (const float*)d_in[5];

    float* outf = (float*)d_out;
    const int n_pos  = BB * 2 * NP;
    const int n_main = BB * C2O * NP;
    const int n_mask = BB * NP;

    float* pos_out  = nullptr;
    float* out_main = outf;
    float* mask_out = nullptr;
    if (out_size == n_pos + n_main + n_mask) {
        pos_out  = outf;
        out_main = outf + n_pos;
        mask_out = out_main + n_main;
    }

    cudaFuncSetAttribute(gemm_hmma_kernel,
                         cudaFuncAttributeMaxDynamicSharedMemorySize, GEMM_SMEM);

    detect_pos_kernel<<<1, 1>>>(pos);
    if (pos_out)
        init_posmask_kernel<<<(BB * NP + 255) / 256, 256>>>(pos_out, mask_out);
    wprep_kernel<<<(C2O + 7) / 8, 256>>>(norm_w, norm_b, red_w);
    scatter_kernel<<<dim3(NN / 32, BB), 256>>>(pos, feat, mask, mask_out);
    stats_kernel<<<(BB * NP + 255) / 256, 256>>>();
    gemm_hmma_kernel<<<dim3(NTILES, BB), 256, GEMM_SMEM>>>(out_main);
}

// round 9
// speedup vs baseline: 8.1335x; 1.1095x over previous
#include <cuda_runtime.h>
#include <cuda_fp16.h>
#include <cstdint>

// Problem constants
#define BB  8
#define CC  96
#define HH  224
#define WW  224
#define NN  (HH*WW)     // 50176
#define H2  112
#define W2  112
#define NP  (H2*W2)     // 12544
#define KK  384         // 4*C
#define C2O 192         // 2*C
#define LN_EPS 1e-5f

#define MT     128               // M tile per block
#define NTILES (NP / MT)         // 98
#define KC     64                // K chunk
#define NCHUNK (KK / KC)         // 6

// ---------------------------------------------------------------------------
// Global scratch
// ---------------------------------------------------------------------------
__device__ __align__(16) __half g_A[(size_t)BB * NP * KK];      // 77 MB masked feat fp16
__device__ __align__(16) __half g_B[(size_t)C2O * KK];          // W' = norm_w * red_w (fp16)
__device__ float  g_s1[C2O];
__device__ float  g_s2[C2O];
__device__ __align__(16) float  g_qstats[(size_t)BB * NP * 4 * 2]; // per-quadrant (sum, sumsq)
__device__ __align__(8)  float2 g_stats[(size_t)BB * NP];          // (mu, rstd)
__device__ int g_pos64;

// ---------------------------------------------------------------------------
// helpers
// ---------------------------------------------------------------------------
__device__ __forceinline__ uint32_t smem_u32(const void* p) {
    uint32_t a;
    asm("{ .reg .u64 t; cvta.to.shared.u64 t, %1; cvt.u32.u64 %0, t; }" : "=r"(a) : "l"(p));
    return a;
}
__device__ __forceinline__ uint32_t swz(uint32_t off) {   // SW128: bits[6:4] ^= bits[9:7]
    return off ^ ((off >> 3) & 0x70);
}
__device__ __forceinline__ void cpa16(uint32_t dst, const void* src) {
    asm volatile("cp.async.cg.shared.global [%0], [%1], 16;" :: "r"(dst), "l"(src) : "memory");
}
#define CP_COMMIT() asm volatile("cp.async.commit_group;" ::: "memory")
template <int N> __device__ __forceinline__ void cp_wait() {
    asm volatile("cp.async.wait_group %0;" :: "n"(N) : "memory");
}
__device__ __forceinline__ void ldm_x4(uint32_t* r, uint32_t addr) {
    asm volatile("ldmatrix.sync.aligned.m8n8.x4.shared.b16 {%0,%1,%2,%3}, [%4];"
                 : "=r"(r[0]), "=r"(r[1]), "=r"(r[2]), "=r"(r[3]) : "r"(addr));
}
__device__ __forceinline__ void ldm_x2(uint32_t* r, uint32_t addr) {
    asm volatile("ldmatrix.sync.aligned.m8n8.x2.shared.b16 {%0,%1}, [%2];"
                 : "=r"(r[0]), "=r"(r[1]) : "r"(addr));
}
__device__ __forceinline__ void mma16816(float* c, const uint32_t* a, const uint32_t* b) {
    asm volatile(
        "mma.sync.aligned.m16n8k16.row.col.f32.f16.f16.f32 "
        "{%0,%1,%2,%3}, {%4,%5,%6,%7}, {%8,%9}, {%0,%1,%2,%3};"
        : "+f"(c[0]), "+f"(c[1]), "+f"(c[2]), "+f"(c[3])
        : "r"(a[0]), "r"(a[1]), "r"(a[2]), "r"(a[3]), "r"(b[0]), "r"(b[1]));
}

// ---------------------------------------------------------------------------
// pos dtype detection
// ---------------------------------------------------------------------------
__global__ void detect_pos_kernel(const void* pos) {
    if (threadIdx.x == 0 && blockIdx.x == 0) {
        const long long* p64 = (const long long*)pos;
        int ok = 1;
        for (int i = 0; i < 64; i++) {
            long long v = p64[i];
            if (v < 0 || v >= 224) { ok = 0; break; }
        }
        g_pos64 = ok;
    }
}

// ---------------------------------------------------------------------------
// pos_out + zero mask_out
// ---------------------------------------------------------------------------
__global__ void init_posmask_kernel(float* pos_out, float* mask_out) {
    int idx = blockIdx.x * blockDim.x + threadIdx.x;
    if (idx >= BB * NP) return;
    int b = idx / NP, p = idx % NP;
    int i = p / W2, j = p % W2;
    pos_out[((size_t)b * 2 + 0) * NP + p] = (float)j;
    pos_out[((size_t)b * 2 + 1) * NP + p] = (float)i;
    mask_out[(size_t)b * NP + p] = 0.0f;
}

// ---------------------------------------------------------------------------
// Scatter-transpose v2: float4 global loads, merged stats+convert+write.
// feat[b][c][n]*mask -> g_A[b][p][q*96+c] (fp16)
// g_qstats[b][p][q] = (sum, sumsq) over that quadrant's 96 channels.
// ---------------------------------------------------------------------------
__global__ __launch_bounds__(256) void scatter_kernel(
    const void* __restrict__ posv,
    const float* __restrict__ feat,
    const float* __restrict__ mask,
    float* mask_out)
{
    __shared__ float tileT[32][97];
    __shared__ float mval[32];
    __shared__ int   dstP[32], dstQ[32];

    int b  = blockIdx.y;
    int n0 = blockIdx.x * 32;
    int t  = threadIdx.x;

    if (t < 32) {
        int n = n0 + t;
        int x, y;
        if (g_pos64) {
            const long long* p64 = (const long long*)posv;
            x = (int)p64[n];
            y = (int)p64[NN + n];
        } else {
            const int* p32 = (const int*)posv;
            x = p32[n];
            y = p32[NN + n];
        }
        int p = (y >> 1) * W2 + (x >> 1);
        int q = (y & 1) + 2 * (x & 1);
        dstP[t] = p;
        dstQ[t] = q;
        float m = mask[(size_t)b * NN + n];
        mval[t] = m;
        if (mask_out)
            atomicMax((unsigned int*)&mask_out[(size_t)b * NP + p],
                      __float_as_uint(m));
    }
    __syncthreads();

    // --- phase 1: float4 loads over n, masked, transpose into smem ---
    {
        const float* fb = feat + (size_t)b * CC * NN;
        int c0 = t >> 3;            // channel 0..31 (+32*it)
        int nb = (t & 7) * 4;       // point base 0..28
        float m0 = mval[nb], m1 = mval[nb + 1], m2 = mval[nb + 2], m3 = mval[nb + 3];
        #pragma unroll
        for (int it = 0; it < 3; it++) {
            int c = c0 + 32 * it;
            float4 v = *(const float4*)(fb + (size_t)c * NN + n0 + nb);
            tileT[nb + 0][c] = v.x * m0;
            tileT[nb + 1][c] = v.y * m1;
            tileT[nb + 2][c] = v.z * m2;
            tileT[nb + 3][c] = v.w * m3;
        }
    }
    __syncthreads();

    // --- phase 2: stats + fp16 convert + scattered 24B writes ---
    {
        int nl = t >> 3;            // point 0..31
        int l8 = t & 7;             // 12-channel slice
        const float* row = tileT[nl] + 12 * l8;

        float s = 0.f, q = 0.f;
        uint2 w[3];
        #pragma unroll
        for (int j = 0; j < 3; j++) {
            float a0 = row[4*j + 0], a1 = row[4*j + 1];
            float a2 = row[4*j + 2], a3 = row[4*j + 3];
            s += (a0 + a1) + (a2 + a3);
            q += a0*a0 + a1*a1 + a2*a2 + a3*a3;
            union { uint2 u; __half2 h[2]; } pk;
            pk.h[0] = __floats2half2_rn(a0, a1);
            pk.h[1] = __floats2half2_rn(a2, a3);
            w[j] = pk.u;
        }
        #pragma unroll
        for (int o = 4; o; o >>= 1) {
            s += __shfl_xor_sync(0xFFFFFFFFu, s, o);
            q += __shfl_xor_sync(0xFFFFFFFFu, q, o);
        }

        unsigned char* dst = (unsigned char*)g_A
            + ((size_t)b * NP + (size_t)dstP[nl]) * (KK * 2)
            + dstQ[nl] * (CC * 2) + l8 * 24;
        *(uint2*)(dst + 0)  = w[0];
        *(uint2*)(dst + 8)  = w[1];
        *(uint2*)(dst + 16) = w[2];

        if (l8 == 0) {
            size_t si = ((size_t)b * NP + dstP[nl]) * 4 + dstQ[nl];
            ((float2*)g_qstats)[si] = make_float2(s, q);
        }
    }
}

// ---------------------------------------------------------------------------
// Fold 4 quadrant partials -> (mu, rstd) per merged pixel.
// ---------------------------------------------------------------------------
__global__ void stats_kernel() {
    int idx = blockIdx.x * blockDim.x + threadIdx.x;
    if (idx >= BB * NP) return;
    const float4* p4 = (const float4*)(g_qstats + (size_t)idx * 8);
    float4 a = p4[0], c = p4[1];
    float s = a.x + a.z + c.x + c.z;
    float q = a.y + a.w + c.y + c.w;
    float mu  = s * (1.f / KK);
    float var = q * (1.f / KK) - mu * mu;
    g_stats[idx] = make_float2(mu, rsqrtf(var + LN_EPS));
}

// ---------------------------------------------------------------------------
// W' = norm_w * red_w (fp16), s1 = sum_k W'(rounded), s2 = sum_k norm_b*red_w
// ---------------------------------------------------------------------------
__global__ __launch_bounds__(256) void wprep_kernel(
    const float* __restrict__ norm_w,
    const float* __restrict__ norm_b,
    const float* __restrict__ red_w)
{
    int wid = threadIdx.x >> 5, lane = threadIdx.x & 31;
    int c = blockIdx.x * 8 + wid;
    if (c >= C2O) return;
    const float* rw = red_w + (size_t)c * KK;
    float s1 = 0.f, s2 = 0.f;
    #pragma unroll
    for (int j = 0; j < 12; j++) {
        int k = lane + 32 * j;
        float w = norm_w[k], r = rw[k];
        __half wh = __float2half_rn(w * r);
        g_B[(size_t)c * KK + k] = wh;
        s1 += __half2float(wh);
        s2 += norm_b[k] * r;
    }
    #pragma unroll
    for (int o = 16; o; o >>= 1) {
        s1 += __shfl_xor_sync(0xFFFFFFFFu, s1, o);
        s2 += __shfl_xor_sync(0xFFFFFFFFu, s2, o);
    }
    if (lane == 0) { g_s1[c] = s1; g_s2[c] = s2; }
}

// ---------------------------------------------------------------------------
// HMMA GEMM on raw masked feat (fp16) with LN folded into the epilogue:
// out[b][c][p] = sc_p * (acc - mu_p * s1[c]) + s2[c]
// Block 128(M) x 192(N); 8 warps = 4(M) x 2(N); 2-stage cp.async, KC=64.
// ---------------------------------------------------------------------------
#define STAGE_A (MT * KC * 2)            // 16384 B
#define STAGE_B (C2O * KC * 2)           // 24576 B
#define STAGE_BYTES (STAGE_A + STAGE_B)  // 40960 B
#define GEMM_SMEM (2 * STAGE_BYTES + MT * 8)   // + 128 float2 stats

__global__ __launch_bounds__(256, 1) void gemm_hmma_kernel(float* __restrict__ out)
{
    extern __shared__ __align__(128) unsigned char smraw[];
    uint32_t base = smem_u32(smraw);
    float2* sMS = (float2*)(smraw + 2 * STAGE_BYTES);

    int t     = threadIdx.x;
    int lane  = t & 31;
    int wid   = t >> 5;
    int ptile = blockIdx.x;
    int b     = blockIdx.y;
    int warp_m = wid >> 1;       // 0..3
    int warp_n = wid & 1;        // 0..1

    if (t < MT) {
        float2 sq = g_stats[(size_t)b * NP + (size_t)ptile * MT + t];
        sMS[t] = sq;
    }

    const __half* Ag = g_A + ((size_t)b * NP + (size_t)ptile * MT) * KK;
    const __half* Bg = g_B;

    auto load_stage = [&](int s, int c) {
        uint32_t st = base + s * STAGE_BYTES;
        const __half* Ac = Ag + c * KC;
        #pragma unroll
        for (int e = t; e < MT * 8; e += 256) {
            int row = e >> 3, ch = e & 7;
            cpa16(st + swz(row * 128 + ch * 16), Ac + (size_t)row * KK + ch * 8);
        }
        const __half* Bc = Bg + c * KC;
        #pragma unroll
        for (int e = t; e < C2O * 8; e += 256) {
            int row = e >> 3, ch = e & 7;
            cpa16(st + STAGE_A + swz(row * 128 + ch * 16), Bc + (size_t)row * KK + ch * 8);
        }
        CP_COMMIT();
    };

    float acc[2][12][4];
    #pragma unroll
    for (int mt = 0; mt < 2; mt++)
        #pragma unroll
        for (int nt = 0; nt < 12; nt++)
            #pragma unroll
            for (int j = 0; j < 4; j++) acc[mt][nt][j] = 0.f;

    load_stage(0, 0);

    int l4 = lane & 15;
    for (int c = 0; c < NCHUNK; c++) {
        if (c + 1 < NCHUNK) { load_stage((c + 1) & 1, c + 1); cp_wait<1>(); }
        else                { cp_wait<0>(); }
        __syncthreads();

        uint32_t Ab = base + (c & 1) * STAGE_BYTES;
        uint32_t Bb = Ab + STAGE_A;

        #pragma unroll
        for (int step = 0; step < 4; step++) {
            int k0 = step * 16;
            uint32_t a[2][4];
            #pragma unroll
            for (int mt = 0; mt < 2; mt++) {
                int row = warp_m * 32 + mt * 16 + l4;
                int kk  = k0 + ((lane >> 4) << 3);
                ldm_x4(a[mt], Ab + swz((uint32_t)(row * 128 + kk * 2)));
            }
            #pragma unroll
            for (int nt = 0; nt < 12; nt++) {
                int n  = warp_n * 96 + nt * 8 + (l4 & 7);
                int kk = k0 + ((l4 >> 3) << 3);
                uint32_t bfr[2];
                ldm_x2(bfr, Bb + swz((uint32_t)(n * 128 + kk * 2)));
                mma16816(acc[0][nt], a[0], bfr);
                mma16816(acc[1][nt], a[1], bfr);
            }
        }
        __syncthreads();
    }

    // --- epilogue with LN folding ---
    int gid  = lane >> 2;
    int tid4 = lane & 3;
    float* ob = out + (size_t)b * C2O * NP;
    #pragma unroll
    for (int mt = 0; mt < 2; mt++) {
        int rl = warp_m * 32 + mt * 16 + gid;
        float2 ms0 = sMS[rl];
        float2 ms1 = sMS[rl + 8];
        int p = ptile * MT + rl;
        #pragma unroll
        for (int nt = 0; nt < 12; nt++) {
            int col = warp_n * 96 + nt * 8 + tid4 * 2;
            float s1a = __ldg(g_s1 + col), s1b = __ldg(g_s1 + col + 1);
            float s2a = __ldg(g_s2 + col), s2b = __ldg(g_s2 + col + 1);
            float* o0 = ob + (size_t)col * NP + p;
            o0[0]      = ms0.y * (acc[mt][nt][0] - ms0.x * s1a) + s2a;
            o0[NP]     = ms0.y * (acc[mt][nt][1] - ms0.x * s1b) + s2b;
            o0[8]      = ms1.y * (acc[mt][nt][2] - ms1.x * s1a) + s2a;
            o0[NP + 8] = ms1.y * (acc[mt][nt][3] - ms1.x * s1b) + s2b;
        }
    }
}

// ---------------------------------------------------------------------------
extern "C" void kernel_launch(void* const* d_in, const int* in_sizes, int n_in,
                              void* d_out, int out_size) {
    const void*  pos    = d_in[0];
    const float* feat   = (const float*)d_in[1];
    const float* mask   = (const float*)d_in[2];
    const float* norm_w = (const float*)d_in[3];
    const float* norm_b = (const float*)d_in[4];
    const float* red_w  = (const float*)d_in[5];

    float* outf = (float*)d_out;
    const int n_pos  = BB * 2 * NP;
    const int n_main = BB * C2O * NP;
    const int n_mask = BB * NP;

    float* pos_out  = nullptr;
    float* out_main = outf;
    float* mask_out = nullptr;
    if (out_size == n_pos + n_main + n_mask) {
        pos_out  = outf;
        out_main = outf + n_pos;
        mask_out = out_main + n_main;
    }

    cudaFuncSetAttribute(gemm_hmma_kernel,
                         cudaFuncAttributeMaxDynamicSharedMemorySize, GEMM_SMEM);

    detect_pos_kernel<<<1, 1>>>(pos);
    if (pos_out)
        init_posmask_kernel<<<(BB * NP + 255) / 256, 256>>>(pos_out, mask_out);
    wprep_kernel<<<(C2O + 7) / 8, 256>>>(norm_w, norm_b, red_w);
    scatter_kernel<<<dim3(NN / 32, BB), 256>>>(pos, feat, mask, mask_out);
    stats_kernel<<<(BB * NP + 255) / 256, 256>>>();
    gemm_hmma_kernel<<<dim3(NTILES, BB), 256, GEMM_SMEM>>>(out_main);
}